// round 5
// baseline (speedup 1.0000x reference)
#include <cuda_runtime.h>
#include <cuda_bf16.h>

// SignAdaptor: fused repeat/gather/concat/pad — persistent chunked kernel.
//   out[b, j, 0:1024]    = image_batch[foff[b] + j]                (j < nf[b])
//   out[b, j, 1024:2048] = clip_batch [coff[b] + min(j/rf, nc-1)]  (j < nf[b])
//   out[b, j, :]         = pad_idx                                 (j >= nf[b])
//   src_length[b]        = nf[b]   (appended after x when present)
//
// Store-bandwidth-bound (~150 MB output; inputs mostly L2-resident across
// replays). One CTA (256 thr) owns a contiguous chunk of CHUNK rows of one
// batch => grid ≈ 1216 CTAs ≈ one full wave on 148 SMs (no wave transitions).
// Clip row is reused in registers across the rf(≈4) rows that share it.

#define B_CONST 32
#define CHUNK   16            // rows per CTA

__global__ __launch_bounds__(256)
void gatherp_kernel(const float* __restrict__ img,
                    const float* __restrict__ clip,
                    const int* __restrict__ nf,
                    const int* __restrict__ nc,
                    const int* __restrict__ pad,   // may be null -> 0
                    float* __restrict__ out,
                    int L, long long src_off, int has_src) {
    const int b  = blockIdx.y;
    const int j0 = blockIdx.x * CHUNK;
    const int t  = threadIdx.x;           // 0..255
    const int lane = t & 31;

    // ---- per-warp redundant exclusive scan of nf/nc over B=32 ----
    int f = nf[lane];
    int c = nc[lane];
    int fs = f, cs = c;
    #pragma unroll
    for (int o = 1; o < 32; o <<= 1) {
        int vf = __shfl_up_sync(0xffffffffu, fs, o);
        int vc = __shfl_up_sync(0xffffffffu, cs, o);
        if (lane >= o) { fs += vf; cs += vc; }
    }
    const int foff_b = __shfl_sync(0xffffffffu, fs - f, b);
    const int coff_b = __shfl_sync(0xffffffffu, cs - c, b);
    const int n      = __shfl_sync(0xffffffffu, f, b);
    const int cnum   = __shfl_sync(0xffffffffu, c, b);

    const int rf   = n / cnum;
    const int cmax = cnum - 1;

    const float  pv = pad ? (float)pad[0] : 0.0f;
    const float4 p4 = make_float4(pv, pv, pv, pv);

    // contiguous output chunk for this CTA
    float4* __restrict__ orow =
        (float4*)(out + ((long long)b * L + j0) * 2048);
    const float4* __restrict__ ib =
        (const float4*)(img + ((long long)(foff_b + j0)) * 1024);

    int    prev_cidx = -1;
    float4 cv = p4;

    #pragma unroll 4
    for (int r = 0; r < CHUNK; r++) {
        const int j = j0 + r;
        if (j >= L) break;

        float4 v0, v1;
        if (j < n) {
            v0 = __ldcs(ib + (long long)r * 256 + t);   // read-once image row
            int cidx = j / rf;
            if (cidx > cmax) cidx = cmax;
            if (cidx != prev_cidx) {                    // clip row reuse (rf≈4)
                cv = __ldg((const float4*)
                           (clip + ((long long)(coff_b + cidx)) * 1024) + t);
                prev_cidx = cidx;
            }
            v1 = cv;
        } else {
            v0 = p4;
            v1 = p4;
        }
        orow[(long long)r * 512 + t]       = v0;
        orow[(long long)r * 512 + 256 + t] = v1;
    }

    if (has_src && j0 == 0 && t == 0) {
        out[src_off + b] = (float)n;
    }
}

extern "C" void kernel_launch(void* const* d_in, const int* in_sizes, int n_in,
                              void* d_out, int out_size) {
    const float* img  = (const float*)d_in[0];   // image_batch [tf, 1024]
    // d_in[1] = emo_batch (unused by reference)
    const float* clip = (const float*)d_in[2];   // clip_batch  [tc, 1024]
    const int*   nf   = (const int*)d_in[3];     // [32]
    const int*   nc   = (const int*)d_in[4];     // [32]
    const int*   pad  = (n_in >= 6) ? (const int*)d_in[5] : nullptr;

    float* out = (float*)d_out;

    // out_size = B*L*2048 (+ B if src_length is part of the flattened output)
    const long long per = (long long)B_CONST * 2048;
    long long L;
    int has_src;
    if ((long long)out_size % per == 0) {
        L = (long long)out_size / per;
        has_src = 0;
    } else {
        L = ((long long)out_size - B_CONST) / per;
        has_src = 1;
    }

    dim3 grid((unsigned)((L + CHUNK - 1) / CHUNK), B_CONST);
    gatherp_kernel<<<grid, 256>>>(img, clip, nf, nc, pad, out,
                                  (int)L, (long long)B_CONST * L * 2048,
                                  has_src);
}

// round 9
// speedup vs baseline: 1.1715x; 1.1715x over previous
#include <cuda_runtime.h>
#include <cuda_bf16.h>

// SignAdaptor: fused repeat/gather/concat/pad — single kernel, 1 row/CTA.
//   out[b, j, 0:1024]    = image_batch[foff[b] + j]                (j < nf[b])
//   out[b, j, 1024:2048] = clip_batch [coff[b] + min(j/rf, nc-1)]  (j < nf[b])
//   out[b, j, :]         = pad_idx                                 (j >= nf[b])
//   src_length[b]        = nf[b]   (appended after x when present)
//
// Write-bandwidth-bound (~156 MB stores; inputs mostly L2-resident across
// replays; measured ceiling ~5.05 TB/s => ~33.4us floor). Best structure is
// 1 row per 256-thread CTA (max cross-CTA memory parallelism). Prefix
// offsets foff[b]/coff[b] computed per-warp with a lane-masked
// __reduce_add_sync (2 REDUX instead of a 20-SHFL scan).

#define B_CONST 32

__global__ __launch_bounds__(256)
void gather1_kernel(const float* __restrict__ img,
                    const float* __restrict__ clip,
                    const int* __restrict__ nf,
                    const int* __restrict__ nc,
                    const int* __restrict__ pad,   // may be null -> 0
                    float* __restrict__ out,
                    int L, long long src_off, int has_src) {
    const int j = blockIdx.x;          // frame position within padded length
    const int b = blockIdx.y;          // batch
    const int t = threadIdx.x;         // 0..255
    const int lane = t & 31;

    // ---- offsets: sum of nf/nc over samples < b (lane-masked reduction) ----
    const int f_lane = nf[lane];                  // coalesced 128B, L1-hit
    const int c_lane = nc[lane];
    const int foff_b = __reduce_add_sync(0xffffffffu, lane < b ? f_lane : 0);
    const int coff_b = __reduce_add_sync(0xffffffffu, lane < b ? c_lane : 0);
    const int n      = __shfl_sync(0xffffffffu, f_lane, b);
    const int cnum   = __shfl_sync(0xffffffffu, c_lane, b);

    float4* __restrict__ orow =
        (float4*)(out + ((long long)b * L + j) * 2048);

    if (j < n) {
        const int rf = n / cnum;
        int cidx = j / rf;
        const int cmax = cnum - 1;
        if (cidx > cmax) cidx = cmax;

        const float4* __restrict__ isrc =
            (const float4*)(img + ((long long)(foff_b + j)) * 1024);
        const float4* __restrict__ csrc =
            (const float4*)(clip + ((long long)(coff_b + cidx)) * 1024);

        orow[t]       = isrc[t];
        orow[256 + t] = csrc[t];
    } else {
        const float pv = pad ? (float)pad[0] : 0.0f;
        const float4 p4 = make_float4(pv, pv, pv, pv);
        orow[t]       = p4;
        orow[256 + t] = p4;
    }

    // src_length tail: one thread per batch row (j==0 blocks).
    if (has_src && j == 0 && t == 0) {
        out[src_off + b] = (float)n;
    }
}

extern "C" void kernel_launch(void* const* d_in, const int* in_sizes, int n_in,
                              void* d_out, int out_size) {
    const float* img  = (const float*)d_in[0];   // image_batch [tf, 1024]
    // d_in[1] = emo_batch (unused by reference)
    const float* clip = (const float*)d_in[2];   // clip_batch  [tc, 1024]
    const int*   nf   = (const int*)d_in[3];     // [32]
    const int*   nc   = (const int*)d_in[4];     // [32]
    const int*   pad  = (n_in >= 6) ? (const int*)d_in[5] : nullptr;

    float* out = (float*)d_out;

    // out_size = B*L*2048 (+ B if src_length is part of the flattened output)
    const long long per = (long long)B_CONST * 2048;
    long long L;
    int has_src;
    if ((long long)out_size % per == 0) {
        L = (long long)out_size / per;
        has_src = 0;
    } else {
        L = ((long long)out_size - B_CONST) / per;
        has_src = 1;
    }

    dim3 grid((unsigned)L, B_CONST);
    gather1_kernel<<<grid, 256>>>(img, clip, nf, nc, pad, out,
                                  (int)L, (long long)B_CONST * L * 2048,
                                  has_src);
}